// round 16
// baseline (speedup 1.0000x reference)
#include <cuda_runtime.h>
#include <cstdint>
#include <math.h>

#define B_  32
#define S_  2048
#define D_  512
#define M_TOTAL (B_ * S_)

// Device scratch (allocation-free): gate logits + fp16-packed weights
// (pre-permuted into the pair-interleaved tile layout, see below).
__device__ float    g_logit[M_TOTAL];
__device__ uint32_t g_Wsh[D_ * D_ / 2];       // fp16 share weights
__device__ uint32_t g_Wlh[8 * D_ * D_ / 2];   // fp16 lang weights
__device__ uint32_t g_W1h[8 * D_ * D_ / 2];   // fp16 gate weights

// ---------------------------------------------------------------------------
// helpers
// ---------------------------------------------------------------------------
__device__ __forceinline__ uint32_t smem_u32(const void* p) {
    uint32_t a;
    asm("{ .reg .u64 t; cvta.to.shared.u64 t, %1; cvt.u32.u64 %0, t; }" : "=r"(a) : "l"(p));
    return a;
}
__device__ __forceinline__ uint32_t f16x2(float hi, float lo) {
    uint32_t r; asm("cvt.rn.f16x2.f32 %0, %1, %2;" : "=r"(r) : "f"(hi), "f"(lo)); return r;
}
__device__ __forceinline__ void mma_f16(float* c, const uint32_t* a, uint32_t b0, uint32_t b1) {
    asm volatile(
        "mma.sync.aligned.m16n8k16.row.col.f32.f16.f16.f32 "
        "{%0,%1,%2,%3}, {%4,%5,%6,%7}, {%8,%9}, {%0,%1,%2,%3};"
        : "+f"(c[0]), "+f"(c[1]), "+f"(c[2]), "+f"(c[3])
        : "r"(a[0]), "r"(a[1]), "r"(a[2]), "r"(a[3]), "r"(b0), "r"(b1));
}
__device__ __forceinline__ void lds64(uint32_t a, uint32_t& x, uint32_t& y) {
    asm volatile("ld.shared.v2.b32 {%0,%1}, [%2];" : "=r"(x), "=r"(y) : "r"(a));
}
__device__ __forceinline__ void sts128(uint32_t a, uint32_t x, uint32_t y, uint32_t z, uint32_t w) {
    asm volatile("st.shared.v4.b32 [%0], {%1,%2,%3,%4};"
                 :: "r"(a), "r"(x), "r"(y), "r"(z), "r"(w) : "memory");
}

#define CP16(d, s)  asm volatile("cp.async.cg.shared.global [%0], [%1], 16;" :: "r"(d), "l"(s))
#define CPCOMMIT()  asm volatile("cp.async.commit_group;" ::: "memory")
#define CPWAIT2()   asm volatile("cp.async.wait_group 2;" ::: "memory")

// ---------------------------------------------------------------------------
// Pair-interleaved fp16 tile layout (K=32 chunks; row = 32 fp16 = 16 u32 = 64B):
//  - within each k16 half (8 u32), logical u32 jl stored at pl = 2*(jl&3)+(jl>>2)
//    so the fragment pair (jl = t, t+4) sits at adjacent u32 (2t, 2t+1) -> LDS.64.
//  - 16B unit u of row r stored at unit u ^ (r & 3)  [period-4 swizzle; verified
//    conflict-free for half-warp LDS.64 phases and quarter-warp STS.128 phases].
// Fragment load (m16n8k16), kstep s, thread (g = lane>>2, t = lane&3):
//    o = ((2s + (t>>1)) ^ (g&3))<<4 | (t&1)<<3 ;  lds64 -> (reg0, reg2);
//    +512B (8 rows) -> (reg1, reg3).  mi step = 1024B (16 rows).
// ---------------------------------------------------------------------------

// ---------------------------------------------------------------------------
// Weight conversion: fp32 -> fp16, written in the pair-interleaved order so
// cp.async unit copies land tile-ready.
// ---------------------------------------------------------------------------
__device__ __forceinline__ uint32_t perm_jr(uint32_t jr) {
    uint32_t c  = jr >> 4, jc = jr & 15u;
    uint32_t jh = jc >> 3, jl = jc & 7u;
    uint32_t pl = 2u * (jl & 3u) + (jl >> 2);
    return (c << 4) + (jh << 3) + pl;
}

__global__ void __launch_bounds__(256) kconv(
    const float* __restrict__ Ws, const float* __restrict__ Wl,
    const float* __restrict__ W1)
{
    int i = blockIdx.x * 256 + threadIdx.x;
    const int NWS = D_ * D_ / 4;
    const int NWL = 8 * D_ * D_ / 4;
    const float4* src; uint32_t* dst; int j;
    if (i < NWS)            { src = (const float4*)Ws; dst = g_Wsh; j = i; }
    else if (i < NWS + NWL) { src = (const float4*)Wl; dst = g_Wlh; j = i - NWS; }
    else                    { src = (const float4*)W1; dst = g_W1h; j = i - NWS - NWL; }
    float4 v = src[j];
    uint32_t o0 = f16x2(v.y, v.x);         // logical u32 2j   (k 4j, 4j+1)
    uint32_t o1 = f16x2(v.w, v.z);         // logical u32 2j+1 (k 4j+2, 4j+3)
    uint32_t row = (uint32_t)j >> 7;       // 128 float4 per 512-col row
    uint32_t jr0 = ((uint32_t)j & 127u) * 2u;
    dst[row * 256u + perm_jr(jr0)]      = o0;
    dst[row * 256u + perm_jr(jr0 + 1u)] = o1;
}

// ---------------------------------------------------------------------------
// A staging (both kernels): thread (ar = tid>>2, agi = tid&3) owns
// k = kb..kb+3 and kb+8..kb+11 where kb = 16*(agi>>1) + 4*(agi&1);
// packs physical unit agi of row ar:  (af1,af0) (af5,af4) (af3,af2) (af7,af6).
// Destination unit = agi ^ (ar & 3).
// ---------------------------------------------------------------------------

// ---------------------------------------------------------------------------
// Kernel 1: gate GEMM in FP16 (old_x @ W1^T) + fused relu/+old_x/.W2 epilogue.
// CTA tile 128x256, warp grid 4m x 4n, warp tile 32x64, occ 1. 16 chunks K=32.
// ---------------------------------------------------------------------------
#define K1_A_STG  8192
#define K1_B_STG  16384
#define K1_SMEM   (K1_A_STG * 2 + K1_B_STG * 4)   // 80KB

__global__ void __launch_bounds__(512, 1) k1_gate(
    const float* __restrict__ old_x, const int* __restrict__ lang,
    const float* __restrict__ gb1,  const float* __restrict__ gW2)
{
    extern __shared__ __align__(128) char dsm[];
    const uint32_t sbA = smem_u32(dsm);
    const uint32_t sbB = sbA + K1_A_STG * 2;

    const int tid  = threadIdx.x;
    const int wid  = tid >> 5, lane = tid & 31;
    const int g    = lane >> 2, t = lane & 3;
    const int wm   = wid & 3,  wn  = wid >> 2;
    const int nt   = blockIdx.x;
    const int rt   = blockIdx.y;
    const int row0 = rt * 128;
    const int n0   = nt * 256;
    const int lg   = lang[rt >> 4];

    const float* gA = old_x + (size_t)row0 * D_;
    const float* b1l = gb1 + lg * D_;
    const float* W2l = gW2 + lg * D_;

    float cc[2][8][4];
    #pragma unroll
    for (int mi = 0; mi < 2; mi++)
        #pragma unroll
        for (int ni = 0; ni < 8; ni++)
            #pragma unroll
            for (int r = 0; r < 4; r++) cc[mi][ni][r] = 0.f;

    const int ar_ = tid >> 2, agi_ = tid & 3;
    const int kb_ = 16 * (agi_ >> 1) + 4 * (agi_ & 1);
    const uint32_t aDst = sbA + (uint32_t)(ar_ * 64 + ((agi_ ^ (ar_ & 3)) << 4));
    const float* aSrc = gA + (size_t)ar_ * D_ + kb_;
    float af[8];

    auto ldgA = [&](int c) {
        float4 v0 = __ldg(reinterpret_cast<const float4*>(aSrc + c * 32));
        float4 v1 = __ldg(reinterpret_cast<const float4*>(aSrc + c * 32 + 8));
        af[0] = v0.x; af[1] = v0.y; af[2] = v0.z; af[3] = v0.w;
        af[4] = v1.x; af[5] = v1.y; af[6] = v1.z; af[7] = v1.w;
    };
    auto stsA = [&](int c) {
        sts128(aDst + (uint32_t)((c & 1) * K1_A_STG),
               f16x2(af[1], af[0]), f16x2(af[5], af[4]),
               f16x2(af[3], af[2]), f16x2(af[7], af[6]));
    };
    const size_t w1Base = ((size_t)lg * 512 + n0) << 8;   // u32 offset; 256 u32/row
    auto issueB = [&](int c) {
        const uint32_t stg = sbB + (uint32_t)((c & 3) * K1_B_STG);
        #pragma unroll
        for (int j = 0; j < 2; j++) {
            const int idx = tid * 2 + j;
            const int n = idx >> 2, gi = idx & 3;
            const uint32_t doff = (uint32_t)(n * 64 + ((gi ^ (n & 3)) << 4));
            CP16(stg + doff, g_W1h + w1Base + (size_t)n * 256 + c * 16 + gi * 4);
        }
    };

    ldgA(0); stsA(0);
    issueB(0); CPCOMMIT();
    issueB(1); CPCOMMIT();
    issueB(2); CPCOMMIT();
    ldgA(1);

    const uint32_t aBase = sbA + (uint32_t)((wm * 32 + g) * 64);
    const uint32_t bBase = sbB + (uint32_t)((wn * 64 + g) * 64);
    const uint32_t g3    = (uint32_t)(g & 3);
    const uint32_t tlow  = (uint32_t)((t & 1) << 3);
    const uint32_t thigh = (uint32_t)(t >> 1);

    #pragma unroll 1
    for (int c = 0; c < 16; c++) {
        CPWAIT2();
        __syncthreads();
        const uint32_t stA = aBase + (uint32_t)((c & 1) * K1_A_STG);
        const uint32_t stB = bBase + (uint32_t)((c & 3) * K1_B_STG);
        #pragma unroll
        for (int s = 0; s < 2; s++) {
            const uint32_t o = ((((uint32_t)(2 * s) + thigh) ^ g3) << 4) + tlow;
            uint32_t a[2][4];
            #pragma unroll
            for (int mi = 0; mi < 2; mi++) {
                const uint32_t ar = stA + (uint32_t)(mi * 1024);
                lds64(ar + o,       a[mi][0], a[mi][2]);
                lds64(ar + 512 + o, a[mi][1], a[mi][3]);
            }
            #pragma unroll
            for (int ni = 0; ni < 8; ni++) {
                uint32_t b0, b1;
                lds64(stB + (uint32_t)(ni * 512) + o, b0, b1);
                mma_f16(cc[0][ni], a[0], b0, b1);
                mma_f16(cc[1][ni], a[1], b0, b1);
            }
        }
        if (c + 1 < 16) stsA(c + 1);
        if (c + 2 < 16) ldgA(c + 2);
        if (c + 3 < 16) issueB(c + 3);
        CPCOMMIT();                 // unconditional: positional group accounting
    }

    #pragma unroll
    for (int mi = 0; mi < 2; mi++) {
        #pragma unroll
        for (int h = 0; h < 2; h++) {
            const int row = row0 + wm * 32 + mi * 16 + h * 8 + g;
            const float* oxr = old_x + (size_t)row * D_;
            float acc = 0.f;
            #pragma unroll
            for (int ni = 0; ni < 8; ni++) {
                const int e = n0 + wn * 64 + ni * 8 + 2 * t;
                float2 b1v = *reinterpret_cast<const float2*>(b1l + e);
                float2 w2v = *reinterpret_cast<const float2*>(W2l + e);
                float2 oxv = *reinterpret_cast<const float2*>(oxr + e);
                acc += (fmaxf(cc[mi][ni][2 * h]     + b1v.x, 0.f) + oxv.x) * w2v.x
                     + (fmaxf(cc[mi][ni][2 * h + 1] + b1v.y, 0.f) + oxv.y) * w2v.y;
            }
            acc += __shfl_xor_sync(0xFFFFFFFFu, acc, 1);
            acc += __shfl_xor_sync(0xFFFFFFFFu, acc, 2);
            if (t == 0) atomicAdd(&g_logit[row], acc);
        }
    }
}

// ---------------------------------------------------------------------------
// Kernel 2: fused dual GEMM in FP16.  out = (x@Ws^T)*(1-gv) + (x@Wl^T)*gv.
// CTA tile 128x128, warp tile 32x32 per GEMM, occ 1. 16 chunks K=32.
// ---------------------------------------------------------------------------
#define K2_A_STG  8192
#define K2_B_STG  16384
#define K2_SMEM   (K2_A_STG * 2 + K2_B_STG * 4)   // 80KB

__global__ void __launch_bounds__(512, 1) k2_fused(
    const float* __restrict__ x, const int* __restrict__ lang,
    const float* __restrict__ gb2, float* __restrict__ out)
{
    extern __shared__ __align__(128) char dsm[];
    const uint32_t sbA = smem_u32(dsm);
    const uint32_t sbB = sbA + K2_A_STG * 2;

    const int tid  = threadIdx.x;
    const int wid  = tid >> 5, lane = tid & 31;
    const int g    = lane >> 2, t = lane & 3;
    const int wm   = wid & 3,  wn  = wid >> 2;
    const int nt   = blockIdx.x;
    const int rt   = blockIdx.y;
    const int row0 = rt * 128;
    const int n0   = nt * 128;
    const int lg   = lang[rt >> 4];

    const float* gA = x + (size_t)row0 * D_;
    const uint32_t* wsB = g_Wsh + (size_t)n0 * 256;
    const uint32_t* wlB = g_Wlh + ((size_t)lg * 512 + n0) * 256;
    const float bb2 = gb2[lg];

    float cs[2][4][4], cl[2][4][4];
    #pragma unroll
    for (int mi = 0; mi < 2; mi++)
        #pragma unroll
        for (int ni = 0; ni < 4; ni++)
            #pragma unroll
            for (int r = 0; r < 4; r++) { cs[mi][ni][r] = 0.f; cl[mi][ni][r] = 0.f; }

    const int ar_ = tid >> 2, agi_ = tid & 3;
    const int kb_ = 16 * (agi_ >> 1) + 4 * (agi_ & 1);
    const uint32_t aDst = sbA + (uint32_t)(ar_ * 64 + ((agi_ ^ (ar_ & 3)) << 4));
    const float* aSrc = gA + (size_t)ar_ * D_ + kb_;
    float af[8];

    auto ldgA = [&](int c) {
        float4 v0 = __ldg(reinterpret_cast<const float4*>(aSrc + c * 32));
        float4 v1 = __ldg(reinterpret_cast<const float4*>(aSrc + c * 32 + 8));
        af[0] = v0.x; af[1] = v0.y; af[2] = v0.z; af[3] = v0.w;
        af[4] = v1.x; af[5] = v1.y; af[6] = v1.z; af[7] = v1.w;
    };
    auto stsA = [&](int c) {
        sts128(aDst + (uint32_t)((c & 1) * K2_A_STG),
               f16x2(af[1], af[0]), f16x2(af[5], af[4]),
               f16x2(af[3], af[2]), f16x2(af[7], af[6]));
    };
    const int bn_ = tid >> 2, bgi_ = tid & 3;
    const uint32_t bDoff = (uint32_t)(bn_ * 64 + ((bgi_ ^ (bn_ & 3)) << 4));
    auto issueB = [&](int c) {
        const uint32_t stg = sbB + (uint32_t)((c & 3) * K2_B_STG);
        const size_t soff = (size_t)bn_ * 256 + c * 16 + bgi_ * 4;
        CP16(stg + bDoff,         wsB + soff);
        CP16(stg + 8192u + bDoff, wlB + soff);
    };

    ldgA(0); stsA(0);
    issueB(0); CPCOMMIT();
    issueB(1); CPCOMMIT();
    issueB(2); CPCOMMIT();
    ldgA(1);

    const uint32_t aBase = sbA + (uint32_t)((wm * 32 + g) * 64);
    const uint32_t sBase = sbB + (uint32_t)((wn * 32 + g) * 64);
    const uint32_t g3    = (uint32_t)(g & 3);
    const uint32_t tlow  = (uint32_t)((t & 1) << 3);
    const uint32_t thigh = (uint32_t)(t >> 1);

    #pragma unroll 1
    for (int c = 0; c < 16; c++) {
        CPWAIT2();
        __syncthreads();
        const uint32_t stA = aBase + (uint32_t)((c & 1) * K2_A_STG);
        const uint32_t stS = sBase + (uint32_t)((c & 3) * K2_B_STG);
        const uint32_t stL = stS + 8192u;
        #pragma unroll
        for (int s = 0; s < 2; s++) {
            const uint32_t o = ((((uint32_t)(2 * s) + thigh) ^ g3) << 4) + tlow;
            uint32_t a[2][4];
            #pragma unroll
            for (int mi = 0; mi < 2; mi++) {
                const uint32_t ar = stA + (uint32_t)(mi * 1024);
                lds64(ar + o,       a[mi][0], a[mi][2]);
                lds64(ar + 512 + o, a[mi][1], a[mi][3]);
            }
            #pragma unroll
            for (int ni = 0; ni < 4; ni++) {
                uint32_t s0, s1, l0, l1;
                lds64(stS + (uint32_t)(ni * 512) + o, s0, s1);
                lds64(stL + (uint32_t)(ni * 512) + o, l0, l1);
                mma_f16(cs[0][ni], a[0], s0, s1);
                mma_f16(cs[1][ni], a[1], s0, s1);
                mma_f16(cl[0][ni], a[0], l0, l1);
                mma_f16(cl[1][ni], a[1], l0, l1);
            }
        }
        if (c + 1 < 16) stsA(c + 1);
        if (c + 2 < 16) ldgA(c + 2);
        if (c + 3 < 16) issueB(c + 3);
        CPCOMMIT();                 // unconditional: positional group accounting
    }

    #pragma unroll
    for (int mi = 0; mi < 2; mi++) {
        #pragma unroll
        for (int h = 0; h < 2; h++) {
            const int row = row0 + wm * 32 + mi * 16 + h * 8 + g;
            const float gv  = 1.f / (1.f + expf(-(g_logit[row] + bb2)));
            const float ngv = 1.f - gv;
            float* o = out + (size_t)row * D_ + n0 + wn * 32;
            #pragma unroll
            for (int ni = 0; ni < 4; ni++) {
                *reinterpret_cast<float2*>(o + ni * 8 + 2 * t) =
                    make_float2(cs[mi][ni][2 * h]     * ngv + cl[mi][ni][2 * h]     * gv,
                                cs[mi][ni][2 * h + 1] * ngv + cl[mi][ni][2 * h + 1] * gv);
            }
        }
    }
}

// ---------------------------------------------------------------------------
// launch
// ---------------------------------------------------------------------------
extern "C" void kernel_launch(void* const* d_in, const int* in_sizes, int n_in,
                              void* d_out, int out_size)
{
    const float* old_x  = (const float*)d_in[0];
    const float* x      = (const float*)d_in[1];
    const int*   lang   = (const int*)  d_in[2];
    const float* shareW = (const float*)d_in[3];
    const float* langsW = (const float*)d_in[4];
    const float* gW1    = (const float*)d_in[5];
    const float* gb1    = (const float*)d_in[6];
    const float* gW2    = (const float*)d_in[7];
    const float* gb2    = (const float*)d_in[8];
    float* out = (float*)d_out;

    cudaFuncSetAttribute(k1_gate,  cudaFuncAttributeMaxDynamicSharedMemorySize, K1_SMEM);
    cudaFuncSetAttribute(k2_fused, cudaFuncAttributeMaxDynamicSharedMemorySize, K2_SMEM);

    void* logit_ptr = nullptr;
    cudaGetSymbolAddress(&logit_ptr, g_logit);
    cudaMemsetAsync(logit_ptr, 0, M_TOTAL * sizeof(float));

    kconv<<<4352, 256>>>(shareW, langsW, gW1);

    k1_gate <<<dim3(2, M_TOTAL / 128), 512, K1_SMEM>>>(old_x, lang, gb1, gW2);
    k2_fused<<<dim3(D_ / 128, M_TOTAL / 128), 512, K2_SMEM>>>(x, lang, gb2, out);
}

// round 17
// speedup vs baseline: 1.0333x; 1.0333x over previous
#include <cuda_runtime.h>
#include <cstdint>
#include <math.h>

#define B_  32
#define S_  2048
#define D_  512
#define M_TOTAL (B_ * S_)
#define K1_CTAS 1024u

// Device scratch (allocation-free): gate logits, completion gate, fp16 weights.
__device__ float    g_logit[M_TOTAL];
__device__ uint32_t g_done;
__device__ uint32_t g_Wsh[D_ * D_ / 2];       // fp16 share weights
__device__ uint32_t g_Wlh[8 * D_ * D_ / 2];   // fp16 lang weights
__device__ uint32_t g_W1h[8 * D_ * D_ / 2];   // fp16 gate weights

// ---------------------------------------------------------------------------
// helpers
// ---------------------------------------------------------------------------
__device__ __forceinline__ uint32_t smem_u32(const void* p) {
    uint32_t a;
    asm("{ .reg .u64 t; cvta.to.shared.u64 t, %1; cvt.u32.u64 %0, t; }" : "=r"(a) : "l"(p));
    return a;
}
__device__ __forceinline__ uint32_t f16x2(float hi, float lo) {
    uint32_t r; asm("cvt.rn.f16x2.f32 %0, %1, %2;" : "=r"(r) : "f"(hi), "f"(lo)); return r;
}
__device__ __forceinline__ void mma_f16(float* c, const uint32_t* a, uint32_t b0, uint32_t b1) {
    asm volatile(
        "mma.sync.aligned.m16n8k16.row.col.f32.f16.f16.f32 "
        "{%0,%1,%2,%3}, {%4,%5,%6,%7}, {%8,%9}, {%0,%1,%2,%3};"
        : "+f"(c[0]), "+f"(c[1]), "+f"(c[2]), "+f"(c[3])
        : "r"(a[0]), "r"(a[1]), "r"(a[2]), "r"(a[3]), "r"(b0), "r"(b1));
}
__device__ __forceinline__ uint32_t lds32(uint32_t a) {
    uint32_t v; asm volatile("ld.shared.b32 %0, [%1];" : "=r"(v) : "r"(a)); return v;
}
__device__ __forceinline__ void sts128(uint32_t a, uint32_t x, uint32_t y, uint32_t z, uint32_t w) {
    asm volatile("st.shared.v4.b32 [%0], {%1,%2,%3,%4};"
                 :: "r"(a), "r"(x), "r"(y), "r"(z), "r"(w) : "memory");
}

#define CP16(d, s)  asm volatile("cp.async.cg.shared.global [%0], [%1], 16;" :: "r"(d), "l"(s))
#define CPCOMMIT()  asm volatile("cp.async.commit_group;" ::: "memory")
#define CPWAIT2()   asm volatile("cp.async.wait_group 2;" ::: "memory")

// ---------------------------------------------------------------------------
// Weight conversion: Ws/Wl/W1 -> packed fp16 (one pass). Also resets g_done.
// ---------------------------------------------------------------------------
__global__ void __launch_bounds__(256) kconv(
    const float* __restrict__ Ws, const float* __restrict__ Wl,
    const float* __restrict__ W1)
{
    if (blockIdx.x == 0 && threadIdx.x == 0) g_done = 0u;
    int i = blockIdx.x * 256 + threadIdx.x;
    const int NWS = D_ * D_ / 4;
    const int NWL = 8 * D_ * D_ / 4;
    const float4* src; uint2* dst; int j;
    if (i < NWS)            { src = (const float4*)Ws; dst = (uint2*)g_Wsh; j = i; }
    else if (i < NWS + NWL) { src = (const float4*)Wl; dst = (uint2*)g_Wlh; j = i - NWS; }
    else                    { src = (const float4*)W1; dst = (uint2*)g_W1h; j = i - NWS - NWL; }
    float4 v = src[j];
    uint2 o; o.x = f16x2(v.y, v.x); o.y = f16x2(v.w, v.z);
    dst[j] = o;
}

// ---------------------------------------------------------------------------
// FP16 smem tile layout (R12-proven): row = 32 fp16 = 16 u32 (64B); 16B unit
// gi of row r stored at unit gi ^ ((r>>1)&3). Fragment (m16n8k16), kstep s,
// thread (g,t): o0 = ((2s+? ) ...) exactly as R12: o0 = ((8s+t)^cA)<<2,
// o1 = o0^16, with cA = ((g>>1)&3)<<2. Conflict-free lds32/STS.128/cp.async.
// ---------------------------------------------------------------------------

#define A_STG  8192
#define B1_STG 16384
#define B2_STG 16384
#define SMEM_TOT (A_STG * 2 + B1_STG * 4)   // 80KB (same both roles)

// ---------------------------------------------------------------------------
// Fused kernel: bid < K1_CTAS -> gate GEMM role; else dual-GEMM role.
// Gate role signals g_done; dual role's epilogue waits for it.
// ---------------------------------------------------------------------------
__global__ void __launch_bounds__(512, 1) k_fused(
    const float* __restrict__ old_x, const float* __restrict__ x,
    const int* __restrict__ lang,
    const float* __restrict__ gb1,  const float* __restrict__ gW2,
    const float* __restrict__ gb2,  float* __restrict__ out)
{
    extern __shared__ __align__(128) char dsm[];
    const uint32_t sbA = smem_u32(dsm);
    const uint32_t sbB = sbA + A_STG * 2;

    const int tid  = threadIdx.x;
    const int wid  = tid >> 5, lane = tid & 31;
    const int g    = lane >> 2, t = lane & 3;
    const int wm   = wid & 3,  wn  = wid >> 2;
    const uint32_t bid = blockIdx.x;

    const int ar_ = tid >> 2, agi_ = tid & 3;
    const uint32_t aDst = sbA + (uint32_t)(ar_ * 64 + ((agi_ ^ ((ar_ >> 1) & 3)) << 4));
    const uint32_t aBase = sbA + (uint32_t)((wm * 32 + g) * 64);
    const uint32_t cA = (uint32_t)(((g >> 1) & 3) << 2);
    float af[8];

    if (bid < K1_CTAS) {
        // ================= gate role (R12 k1_gate) =================
        const int nt   = (int)(bid & 1u);
        const int rt   = (int)(bid >> 1);
        const int row0 = rt * 128;
        const int n0   = nt * 256;
        const int lg   = lang[rt >> 4];

        const float* gA  = old_x + (size_t)row0 * D_;
        const float* b1l = gb1 + lg * D_;
        const float* W2l = gW2 + lg * D_;

        float cc[2][8][4];
        #pragma unroll
        for (int mi = 0; mi < 2; mi++)
            #pragma unroll
            for (int ni = 0; ni < 8; ni++)
                #pragma unroll
                for (int r = 0; r < 4; r++) cc[mi][ni][r] = 0.f;

        const float* aSrc = gA + (size_t)ar_ * D_ + agi_ * 8;
        auto ldgA = [&](int c) {
            const float4* p = reinterpret_cast<const float4*>(aSrc + c * 32);
            float4 v0 = __ldg(p), v1 = __ldg(p + 1);
            af[0] = v0.x; af[1] = v0.y; af[2] = v0.z; af[3] = v0.w;
            af[4] = v1.x; af[5] = v1.y; af[6] = v1.z; af[7] = v1.w;
        };
        auto stsA = [&](int c) {
            sts128(aDst + (uint32_t)((c & 1) * A_STG),
                   f16x2(af[1], af[0]), f16x2(af[3], af[2]),
                   f16x2(af[5], af[4]), f16x2(af[7], af[6]));
        };
        const size_t w1Base = ((size_t)lg * 512 + n0) << 8;
        auto issueB = [&](int c) {
            const uint32_t stg = sbB + (uint32_t)((c & 3) * B1_STG);
            #pragma unroll
            for (int j = 0; j < 2; j++) {
                const int idx = tid * 2 + j;
                const int n = idx >> 2, gi = idx & 3;
                const uint32_t doff = (uint32_t)(n * 64 + ((gi ^ ((n >> 1) & 3)) << 4));
                CP16(stg + doff, g_W1h + w1Base + (size_t)n * 256 + c * 16 + gi * 4);
            }
        };

        ldgA(0); stsA(0);
        issueB(0); CPCOMMIT();
        issueB(1); CPCOMMIT();
        issueB(2); CPCOMMIT();
        ldgA(1);

        const uint32_t bBase = sbB + (uint32_t)((wn * 64 + g) * 64);

        #pragma unroll 1
        for (int c = 0; c < 16; c++) {
            CPWAIT2();
            __syncthreads();
            const uint32_t stA = aBase + (uint32_t)((c & 1) * A_STG);
            const uint32_t stB = bBase + (uint32_t)((c & 3) * B1_STG);
            #pragma unroll
            for (int s = 0; s < 2; s++) {
                const uint32_t o0 = (((uint32_t)(8 * s + t)) ^ cA) << 2;
                const uint32_t o1 = o0 ^ 16;
                uint32_t a[2][4];
                #pragma unroll
                for (int mi = 0; mi < 2; mi++) {
                    const uint32_t ar = stA + (uint32_t)(mi * 1024);
                    a[mi][0] = lds32(ar + o0);
                    a[mi][1] = lds32(ar + 512 + o0);
                    a[mi][2] = lds32(ar + o1);
                    a[mi][3] = lds32(ar + 512 + o1);
                }
                #pragma unroll
                for (int ni = 0; ni < 8; ni++) {
                    const uint32_t br = stB + (uint32_t)(ni * 512);
                    const uint32_t b0 = lds32(br + o0);
                    const uint32_t b1 = lds32(br + o1);
                    mma_f16(cc[0][ni], a[0], b0, b1);
                    mma_f16(cc[1][ni], a[1], b0, b1);
                }
            }
            if (c + 1 < 16) stsA(c + 1);
            if (c + 2 < 16) ldgA(c + 2);
            if (c + 3 < 16) issueB(c + 3);
            CPCOMMIT();
        }

        #pragma unroll
        for (int mi = 0; mi < 2; mi++) {
            #pragma unroll
            for (int h = 0; h < 2; h++) {
                const int row = row0 + wm * 32 + mi * 16 + h * 8 + g;
                const float* oxr = old_x + (size_t)row * D_;
                float acc = 0.f;
                #pragma unroll
                for (int ni = 0; ni < 8; ni++) {
                    const int e = n0 + wn * 64 + ni * 8 + 2 * t;
                    float2 b1v = *reinterpret_cast<const float2*>(b1l + e);
                    float2 w2v = *reinterpret_cast<const float2*>(W2l + e);
                    float2 oxv = *reinterpret_cast<const float2*>(oxr + e);
                    acc += (fmaxf(cc[mi][ni][2 * h]     + b1v.x, 0.f) + oxv.x) * w2v.x
                         + (fmaxf(cc[mi][ni][2 * h + 1] + b1v.y, 0.f) + oxv.y) * w2v.y;
                }
                acc += __shfl_xor_sync(0xFFFFFFFFu, acc, 1);
                acc += __shfl_xor_sync(0xFFFFFFFFu, acc, 2);
                if (t == 0) atomicAdd(&g_logit[row], acc);
            }
        }

        // signal completion (release)
        __syncthreads();
        if (tid == 0) {
            __threadfence();
            atomicAdd(&g_done, 1u);
        }
    } else {
        // ================= dual-GEMM role (R12 k2_fused) =================
        const uint32_t kb = bid - K1_CTAS;
        const int nt   = (int)(kb & 3u);
        const int rt   = (int)(kb >> 2);
        const int row0 = rt * 128;
        const int n0   = nt * 128;
        const int lg   = lang[rt >> 4];

        const float* gA = x + (size_t)row0 * D_;
        const uint32_t* wsB = g_Wsh + (size_t)n0 * 256;
        const uint32_t* wlB = g_Wlh + ((size_t)lg * 512 + n0) * 256;
        const float bb2 = gb2[lg];

        float cs[2][4][4], cl[2][4][4];
        #pragma unroll
        for (int mi = 0; mi < 2; mi++)
            #pragma unroll
            for (int ni = 0; ni < 4; ni++)
                #pragma unroll
                for (int r = 0; r < 4; r++) { cs[mi][ni][r] = 0.f; cl[mi][ni][r] = 0.f; }

        const float* aSrc = gA + (size_t)ar_ * D_ + agi_ * 8;
        auto ldgA = [&](int c) {
            const float4* p = reinterpret_cast<const float4*>(aSrc + c * 32);
            float4 v0 = __ldg(p), v1 = __ldg(p + 1);
            af[0] = v0.x; af[1] = v0.y; af[2] = v0.z; af[3] = v0.w;
            af[4] = v1.x; af[5] = v1.y; af[6] = v1.z; af[7] = v1.w;
        };
        auto stsA = [&](int c) {
            sts128(aDst + (uint32_t)((c & 1) * A_STG),
                   f16x2(af[1], af[0]), f16x2(af[3], af[2]),
                   f16x2(af[5], af[4]), f16x2(af[7], af[6]));
        };
        const int bn_ = tid >> 2, bgi_ = tid & 3;
        const uint32_t bDoff = (uint32_t)(bn_ * 64 + ((bgi_ ^ ((bn_ >> 1) & 3)) << 4));
        auto issueB = [&](int c) {
            const uint32_t stg = sbB + (uint32_t)((c & 3) * B2_STG);
            const size_t soff = (size_t)bn_ * 256 + c * 16 + bgi_ * 4;
            CP16(stg + bDoff,         wsB + soff);
            CP16(stg + 8192u + bDoff, wlB + soff);
        };

        ldgA(0); stsA(0);
        issueB(0); CPCOMMIT();
        issueB(1); CPCOMMIT();
        issueB(2); CPCOMMIT();
        ldgA(1);

        const uint32_t sBase = sbB + (uint32_t)((wn * 32 + g) * 64);

        #pragma unroll 1
        for (int c = 0; c < 16; c++) {
            CPWAIT2();
            __syncthreads();
            const uint32_t stA = aBase + (uint32_t)((c & 1) * A_STG);
            const uint32_t stS = sBase + (uint32_t)((c & 3) * B2_STG);
            const uint32_t stL = stS + 8192u;
            #pragma unroll
            for (int s = 0; s < 2; s++) {
                const uint32_t o0 = (((uint32_t)(8 * s + t)) ^ cA) << 2;
                const uint32_t o1 = o0 ^ 16;
                uint32_t a[2][4];
                #pragma unroll
                for (int mi = 0; mi < 2; mi++) {
                    const uint32_t ar = stA + (uint32_t)(mi * 1024);
                    a[mi][0] = lds32(ar + o0);
                    a[mi][1] = lds32(ar + 512 + o0);
                    a[mi][2] = lds32(ar + o1);
                    a[mi][3] = lds32(ar + 512 + o1);
                }
                #pragma unroll
                for (int ni = 0; ni < 4; ni++) {
                    const uint32_t srS = stS + (uint32_t)(ni * 512);
                    const uint32_t srL = stL + (uint32_t)(ni * 512);
                    const uint32_t s0 = lds32(srS + o0);
                    const uint32_t s1 = lds32(srS + o1);
                    const uint32_t l0 = lds32(srL + o0);
                    const uint32_t l1 = lds32(srL + o1);
                    mma_f16(cs[0][ni], a[0], s0, s1);
                    mma_f16(cs[1][ni], a[1], s0, s1);
                    mma_f16(cl[0][ni], a[0], l0, l1);
                    mma_f16(cl[1][ni], a[1], l0, l1);
                }
            }
            if (c + 1 < 16) stsA(c + 1);
            if (c + 2 < 16) ldgA(c + 2);
            if (c + 3 < 16) issueB(c + 3);
            CPCOMMIT();
        }

        // wait for all gate CTAs (acquire) before reading g_logit
        if (tid == 0) {
            uint32_t d;
            do {
                asm volatile("ld.acquire.gpu.b32 %0, [%1];" : "=r"(d) : "l"(&g_done));
                if (d < K1_CTAS) __nanosleep(200);
            } while (d < K1_CTAS);
        }
        __syncthreads();

        #pragma unroll
        for (int mi = 0; mi < 2; mi++) {
            #pragma unroll
            for (int h = 0; h < 2; h++) {
                const int row = row0 + wm * 32 + mi * 16 + h * 8 + g;
                const float gv  = 1.f / (1.f + expf(-(__ldcg(&g_logit[row]) + bb2)));
                const float ngv = 1.f - gv;
                float* o = out + (size_t)row * D_ + n0 + wn * 32;
                #pragma unroll
                for (int ni = 0; ni < 4; ni++) {
                    *reinterpret_cast<float2*>(o + ni * 8 + 2 * t) =
                        make_float2(cs[mi][ni][2 * h]     * ngv + cl[mi][ni][2 * h]     * gv,
                                    cs[mi][ni][2 * h + 1] * ngv + cl[mi][ni][2 * h + 1] * gv);
                }
            }
        }
    }
}

// ---------------------------------------------------------------------------
// launch
// ---------------------------------------------------------------------------
extern "C" void kernel_launch(void* const* d_in, const int* in_sizes, int n_in,
                              void* d_out, int out_size)
{
    const float* old_x  = (const float*)d_in[0];
    const float* x      = (const float*)d_in[1];
    const int*   lang   = (const int*)  d_in[2];
    const float* shareW = (const float*)d_in[3];
    const float* langsW = (const float*)d_in[4];
    const float* gW1    = (const float*)d_in[5];
    const float* gb1    = (const float*)d_in[6];
    const float* gW2    = (const float*)d_in[7];
    const float* gb2    = (const float*)d_in[8];
    float* out = (float*)d_out;

    cudaFuncSetAttribute(k_fused, cudaFuncAttributeMaxDynamicSharedMemorySize, SMEM_TOT);

    void* logit_ptr = nullptr;
    cudaGetSymbolAddress(&logit_ptr, g_logit);
    cudaMemsetAsync(logit_ptr, 0, M_TOTAL * sizeof(float));

    kconv<<<4352, 256>>>(shareW, langsW, gW1);   // also resets g_done

    k_fused<<<K1_CTAS + 2048, 512, SMEM_TOT>>>(old_x, x, lang, gb1, gW2, gb2, out);
}